// round 15
// baseline (speedup 1.0000x reference)
#include <cuda_runtime.h>
#include <math.h>
#include <stdint.h>

#define NBB 64      // batch
#define NSS 64      // src len
#define NTT 64      // trg len
#define NEE 1024    // embed dim
#define NHH 1024    // hidden
#define NGG 3072    // 3*H
#define NVV 32000   // vocab

// ---------------- scratch (device globals; no cudaMalloc allowed) ------------
__device__ float g_gi_enc[NSS * NBB * NGG];          // enc layer0 x-projection, all t
__device__ float g_gi_dec[(NTT - 1) * NBB * NGG];    // dec layer0 x-projection, all t
__device__ float g_hbuf[2 * 2 * NBB * NHH];          // [pingpong][layer][B*H]
__device__ float g_x1[NBB * NHH];                    // layer0 -> layer1 input
__device__ float g_top[(NTT - 1) * NBB * NHH];       // decoder top hidden states

// ---------------- small utility kernels --------------------------------------
__global__ void k_zero(float* p, int n) {
    int i = blockIdx.x * blockDim.x + threadIdx.x;
    if (i < n) p[i] = 0.0f;
}

__global__ void k_zero_out_t0(float* out) {
    int i = blockIdx.x * blockDim.x + threadIdx.x;
    if (i < NBB * NVV) {
        int b = i / NVV, v = i - b * NVV;
        out[(size_t)b * NTT * NVV + v] = 0.0f;
    }
}

// ---------------- embedding-gather GEMM ---------------------------------------
// C[(t*64 + b)*NG + j] = dot(emb[tokens[b*tokStride + t]], W[j, :])
// One block per (t, 64-wide j tile). 64x64 tile, 4x4 micro, Ktile=16.
__global__ __launch_bounds__(256) void k_embed_gemm(
    const int* __restrict__ tokens, int tokStride,
    const float* __restrict__ emb,      // [V, E]
    const float* __restrict__ W,        // [3H, E]
    float* __restrict__ C)              // [steps*64, 3H]
{
    __shared__ __align__(16) float As[16][68];
    __shared__ __align__(16) float Bs[16][68];
    __shared__ int tok_s[64];

    int t  = blockIdx.x;
    int n0 = blockIdx.y * 64;
    int tid = threadIdx.x;
    int ty = tid >> 4, tx = tid & 15;

    if (tid < 64) tok_s[tid] = tokens[tid * tokStride + t];
    __syncthreads();

    float acc[4][4] = {};
    for (int k0 = 0; k0 < NEE; k0 += 16) {
        #pragma unroll
        for (int e = tid; e < 1024; e += 256) {
            int r = e >> 4, k = e & 15;
            As[k][r] = emb[(size_t)tok_s[r] * NEE + k0 + k];
            Bs[k][r] = W[(size_t)(n0 + r) * NEE + k0 + k];
        }
        __syncthreads();
        #pragma unroll
        for (int kk = 0; kk < 16; kk++) {
            float4 a4 = *(const float4*)&As[kk][4 * ty];
            float4 b4 = *(const float4*)&Bs[kk][4 * tx];
            float av[4] = {a4.x, a4.y, a4.z, a4.w};
            float bv[4] = {b4.x, b4.y, b4.z, b4.w};
            #pragma unroll
            for (int r = 0; r < 4; r++)
                #pragma unroll
                for (int c = 0; c < 4; c++)
                    acc[r][c] += av[r] * bv[c];
        }
        __syncthreads();
    }

    size_t mbase = (size_t)t * NBB;
    #pragma unroll
    for (int r = 0; r < 4; r++) {
        int b = 4 * ty + r;
        #pragma unroll
        for (int c = 0; c < 4; c++)
            C[(mbase + b) * NGG + n0 + 4 * tx + c] = acc[r][c];
    }
}

// ---------------- fused GRU layer step ----------------------------------------
// Block covers rows b0..b0+31 and gate columns {i0..i0+15} for all 3 gates
// (48 effective N columns). Two K=1024 passes:
//   SX = x-part  (precomputed gi for layer0, or x@Wih^T for layer1)
//   SH = h-part  (h@Whh^T)
// Then GRU pointwise: r=sig(SXr+SHr+b), z=sig(..), n=tanh(SXn+bihn + r*(SHn+bhhn))
// h' = (1-z)n + z h ; encoder mask freezes h where t >= len[b].
__global__ __launch_bounds__(256) void k_gru_layer(
    const float* __restrict__ gi,    // layer0: precomputed x-proj for this step; else null
    const float* __restrict__ xin,   // layer1: input rows [B,H]; else null
    const float* __restrict__ Wih,   // [3H,H] (used iff xin)
    const float* __restrict__ Whh,   // [3H,H]
    const float* __restrict__ bih,   // [3H]
    const float* __restrict__ bhh,   // [3H]
    const float* __restrict__ hin,   // [B,H] old hidden
    float* __restrict__ hout,        // [B,H] new hidden (other pingpong buf)
    float* __restrict__ xout,        // raw new hidden (layer input / top stash) or null
    const int* __restrict__ lens,    // encoder mask or null
    int t)
{
    __shared__ float SX[32][48];
    __shared__ float SH[32][48];
    __shared__ float As[16][33];
    __shared__ float Bs[16][49];

    int tid = threadIdx.x;
    int ty = tid >> 4, tx = tid & 15;
    int i0 = blockIdx.x * 16;
    int b0 = blockIdx.y * 32;

    // ---- phase 1: SX ----
    if (gi) {
        for (int e = tid; e < 32 * 48; e += 256) {
            int rl = e / 48, c = e - rl * 48;
            int j = ((c >> 4) << 10) + i0 + (c & 15);
            SX[rl][c] = gi[(size_t)(b0 + rl) * NGG + j];
        }
    } else {
        float acc[2][3] = {};
        for (int k0 = 0; k0 < NHH; k0 += 16) {
            #pragma unroll
            for (int e = tid; e < 512; e += 256) {
                int r = e >> 4, k = e & 15;
                As[k][r] = xin[(size_t)(b0 + r) * NHH + k0 + k];
            }
            #pragma unroll
            for (int e = tid; e < 768; e += 256) {
                int c = e >> 4, k = e & 15;
                int j = ((c >> 4) << 10) + i0 + (c & 15);
                Bs[k][c] = Wih[(size_t)j * NHH + k0 + k];
            }
            __syncthreads();
            #pragma unroll
            for (int kk = 0; kk < 16; kk++) {
                float a0 = As[kk][2 * ty], a1 = As[kk][2 * ty + 1];
                float w0 = Bs[kk][3 * tx], w1 = Bs[kk][3 * tx + 1], w2 = Bs[kk][3 * tx + 2];
                acc[0][0] += a0 * w0; acc[0][1] += a0 * w1; acc[0][2] += a0 * w2;
                acc[1][0] += a1 * w0; acc[1][1] += a1 * w1; acc[1][2] += a1 * w2;
            }
            __syncthreads();
        }
        #pragma unroll
        for (int r = 0; r < 2; r++)
            #pragma unroll
            for (int c = 0; c < 3; c++)
                SX[2 * ty + r][3 * tx + c] = acc[r][c];
    }
    __syncthreads();

    // ---- phase 2: SH = h @ Whh^T ----
    {
        float acc[2][3] = {};
        for (int k0 = 0; k0 < NHH; k0 += 16) {
            #pragma unroll
            for (int e = tid; e < 512; e += 256) {
                int r = e >> 4, k = e & 15;
                As[k][r] = hin[(size_t)(b0 + r) * NHH + k0 + k];
            }
            #pragma unroll
            for (int e = tid; e < 768; e += 256) {
                int c = e >> 4, k = e & 15;
                int j = ((c >> 4) << 10) + i0 + (c & 15);
                Bs[k][c] = Whh[(size_t)j * NHH + k0 + k];
            }
            __syncthreads();
            #pragma unroll
            for (int kk = 0; kk < 16; kk++) {
                float a0 = As[kk][2 * ty], a1 = As[kk][2 * ty + 1];
                float w0 = Bs[kk][3 * tx], w1 = Bs[kk][3 * tx + 1], w2 = Bs[kk][3 * tx + 2];
                acc[0][0] += a0 * w0; acc[0][1] += a0 * w1; acc[0][2] += a0 * w2;
                acc[1][0] += a1 * w0; acc[1][1] += a1 * w1; acc[1][2] += a1 * w2;
            }
            __syncthreads();
        }
        #pragma unroll
        for (int r = 0; r < 2; r++)
            #pragma unroll
            for (int c = 0; c < 3; c++)
                SH[2 * ty + r][3 * tx + c] = acc[r][c];
    }
    __syncthreads();

    // ---- phase 3: GRU pointwise + masked state update ----
    for (int p = tid; p < 512; p += 256) {
        int rl = p >> 4, il = p & 15;
        int b = b0 + rl, i = i0 + il;
        float xr = SX[rl][il]        + bih[i];
        float xz = SX[rl][16 + il]   + bih[NHH + i];
        float xn = SX[rl][32 + il]   + bih[2 * NHH + i];
        float hr = SH[rl][il]        + bhh[i];
        float hz = SH[rl][16 + il]   + bhh[NHH + i];
        float hn = SH[rl][32 + il]   + bhh[2 * NHH + i];
        float r = 1.0f / (1.0f + expf(-(xr + hr)));
        float z = 1.0f / (1.0f + expf(-(xz + hz)));
        float n = tanhf(xn + r * hn);
        float hold = hin[(size_t)b * NHH + i];
        float hnew = (1.0f - z) * n + z * hold;
        float hw = hnew;
        if (lens && !(t < lens[b])) hw = hold;   // freeze past sequence end
        hout[(size_t)b * NHH + i] = hw;
        if (xout) xout[(size_t)b * NHH + i] = hnew;  // raw output feeds next layer
    }
}

// ---------------- output projection GEMM --------------------------------------
// logits[m, n] = dot(top[m,:], Wout[n,:]) + bout[n], m = t*64 + b (t in 0..62)
// scattered to out[b, t+1, n].
__global__ __launch_bounds__(256) void k_out_gemm(
    const float* __restrict__ A,     // g_top [4032, 1024]
    const float* __restrict__ W,     // Wout  [32000, 1024]
    const float* __restrict__ bo,    // [32000]
    float* __restrict__ out)         // [B, T, V]
{
    __shared__ __align__(16) float As[16][68];
    __shared__ __align__(16) float Bs[16][68];

    int m0 = blockIdx.x * 64;
    int n0 = blockIdx.y * 64;
    int tid = threadIdx.x;
    int ty = tid >> 4, tx = tid & 15;

    float acc[4][4] = {};
    for (int k0 = 0; k0 < NHH; k0 += 16) {
        #pragma unroll
        for (int e = tid; e < 1024; e += 256) {
            int r = e >> 4, k = e & 15;
            As[k][r] = A[(size_t)(m0 + r) * NHH + k0 + k];
            Bs[k][r] = W[(size_t)(n0 + r) * NHH + k0 + k];
        }
        __syncthreads();
        #pragma unroll
        for (int kk = 0; kk < 16; kk++) {
            float4 a4 = *(const float4*)&As[kk][4 * ty];
            float4 b4 = *(const float4*)&Bs[kk][4 * tx];
            float av[4] = {a4.x, a4.y, a4.z, a4.w};
            float bv[4] = {b4.x, b4.y, b4.z, b4.w};
            #pragma unroll
            for (int r = 0; r < 4; r++)
                #pragma unroll
                for (int c = 0; c < 4; c++)
                    acc[r][c] += av[r] * bv[c];
        }
        __syncthreads();
    }

    #pragma unroll
    for (int r = 0; r < 4; r++) {
        int m = m0 + 4 * ty + r;
        int b = m & 63;
        int t = m >> 6;                  // 0..62
        size_t obase = (size_t)b * NTT * NVV + (size_t)(t + 1) * NVV;
        #pragma unroll
        for (int c = 0; c < 4; c++) {
            int n = n0 + 4 * tx + c;
            out[obase + n] = acc[r][c] + bo[n];
        }
    }
}

// ---------------- launch ------------------------------------------------------
extern "C" void kernel_launch(void* const* d_in, const int* in_sizes, int n_in,
                              void* d_out, int out_size)
{
    const int*   src_tokens  = (const int*)d_in[0];
    const int*   src_lengths = (const int*)d_in[1];
    const int*   trg         = (const int*)d_in[2];
    const float* emb_enc     = (const float*)d_in[3];
    const float* Wih_enc     = (const float*)d_in[4];
    const float* Whh_enc     = (const float*)d_in[5];
    const float* bih_enc     = (const float*)d_in[6];
    const float* bhh_enc     = (const float*)d_in[7];
    const float* emb_dec     = (const float*)d_in[8];
    const float* Wih_dec     = (const float*)d_in[9];
    const float* Whh_dec     = (const float*)d_in[10];
    const float* bih_dec     = (const float*)d_in[11];
    const float* bhh_dec     = (const float*)d_in[12];
    const float* Wout        = (const float*)d_in[13];
    const float* bout        = (const float*)d_in[14];
    float* out = (float*)d_out;

    float *gi_enc, *gi_dec, *hbuf, *x1, *top;
    cudaGetSymbolAddress((void**)&gi_enc, g_gi_enc);
    cudaGetSymbolAddress((void**)&gi_dec, g_gi_dec);
    cudaGetSymbolAddress((void**)&hbuf,  g_hbuf);
    cudaGetSymbolAddress((void**)&x1,    g_x1);
    cudaGetSymbolAddress((void**)&top,   g_top);

    const int HB = NBB * NHH;   // 65536 floats per (layer) hidden

    // initial hidden (pingpong buf 0, both layers) and out[:,0,:]
    k_zero<<<(2 * HB + 255) / 256, 256>>>(hbuf, 2 * HB);
    k_zero_out_t0<<<(NBB * NVV + 255) / 256, 256>>>(out);

    // encoder layer-0 input projections for all timesteps (one big GEMM)
    dim3 eg(NSS, NGG / 64);
    k_embed_gemm<<<eg, 256>>>(src_tokens, NSS, emb_enc, Wih_enc, gi_enc);

    dim3 gg(NHH / 16, 2);
    for (int t = 0; t < NSS; t++) {
        float* hr = hbuf + (size_t)(t & 1) * 2 * HB;
        float* hw = hbuf + (size_t)((t + 1) & 1) * 2 * HB;
        // layer 0
        k_gru_layer<<<gg, 256>>>(gi_enc + (size_t)t * NBB * NGG, nullptr,
                                 nullptr, Whh_enc, bih_enc, bhh_enc,
                                 hr, hw, x1, src_lengths, t);
        // layer 1
        k_gru_layer<<<gg, 256>>>(nullptr, x1,
                                 Wih_enc + (size_t)NGG * NEE, Whh_enc + (size_t)NGG * NHH,
                                 bih_enc + NGG, bhh_enc + NGG,
                                 hr + HB, hw + HB, nullptr, src_lengths, t);
    }

    // decoder layer-0 input projections (teacher forcing: tokens known upfront)
    dim3 dg(NTT - 1, NGG / 64);
    k_embed_gemm<<<dg, 256>>>(trg, NTT, emb_dec, Wih_dec, gi_dec);

    for (int k = 0; k < NTT - 1; k++) {
        float* hr = hbuf + (size_t)(k & 1) * 2 * HB;
        float* hw = hbuf + (size_t)((k + 1) & 1) * 2 * HB;
        k_gru_layer<<<gg, 256>>>(gi_dec + (size_t)k * NBB * NGG, nullptr,
                                 nullptr, Whh_dec, bih_dec, bhh_dec,
                                 hr, hw, x1, nullptr, k);
        k_gru_layer<<<gg, 256>>>(nullptr, x1,
                                 Wih_dec + (size_t)NGG * NEE, Whh_dec + (size_t)NGG * NHH,
                                 bih_dec + NGG, bhh_dec + NGG,
                                 hr + HB, hw + HB, top + (size_t)k * HB, nullptr, k);
    }

    // one deferred output projection over all decoder steps
    dim3 og((NTT - 1) * NBB / 64, NVV / 64);   // (63, 500)
    k_out_gemm<<<og, 256>>>(top, Wout, bout, out);
}

// round 16
// speedup vs baseline: 1.2195x; 1.2195x over previous
#include <cuda_runtime.h>
#include <math.h>
#include <stdint.h>

#define NBB 64      // batch
#define NSS 64      // src len
#define NTT 64      // trg len
#define NEE 1024    // embed dim
#define NHH 1024    // hidden
#define NGG 3072    // 3*H
#define NVV 32000   // vocab

// ---------------- scratch (device globals; no cudaMalloc allowed) ------------
__device__ float g_gi_enc[NSS * NBB * NGG];          // enc layer0 x-projection, all t
__device__ float g_gi_dec[(NTT - 1) * NBB * NGG];    // dec layer0 x-projection, all t
__device__ float g_hbuf[2 * 2 * NBB * NHH];          // [pingpong][layer][B*H]
__device__ float g_x1[NBB * NHH];                    // layer0 -> layer1 input
__device__ float g_top[(NTT - 1) * NBB * NHH];       // decoder top hidden states

// ---------------- small utility kernels --------------------------------------
__global__ void k_zero(float* p, int n) {
    int i = blockIdx.x * blockDim.x + threadIdx.x;
    if (i < n) p[i] = 0.0f;
}

__global__ void k_zero_out_t0(float* out) {
    int i = blockIdx.x * blockDim.x + threadIdx.x;
    if (i < NBB * NVV) {
        int b = i / NVV, v = i - b * NVV;
        out[(size_t)b * NTT * NVV + v] = 0.0f;
    }
}

// ---------------- embedding-gather GEMM ---------------------------------------
// C[(t*64 + b)*NG + j] = dot(emb[tokens[b*tokStride + t]], W[j, :])
__global__ __launch_bounds__(256) void k_embed_gemm(
    const int* __restrict__ tokens, int tokStride,
    const float* __restrict__ emb,      // [V, E]
    const float* __restrict__ W,        // [3H, E]
    float* __restrict__ C)              // [steps*64, 3H]
{
    __shared__ __align__(16) float As[16][68];
    __shared__ __align__(16) float Bs[16][68];
    __shared__ int tok_s[64];

    int t  = blockIdx.x;
    int n0 = blockIdx.y * 64;
    int tid = threadIdx.x;
    int ty = tid >> 4, tx = tid & 15;

    if (tid < 64) tok_s[tid] = tokens[tid * tokStride + t];
    __syncthreads();

    float acc[4][4] = {};
    for (int k0 = 0; k0 < NEE; k0 += 16) {
        #pragma unroll
        for (int e = tid; e < 1024; e += 256) {
            int r = e >> 4, k = e & 15;
            As[k][r] = emb[(size_t)tok_s[r] * NEE + k0 + k];
            Bs[k][r] = W[(size_t)(n0 + r) * NEE + k0 + k];
        }
        __syncthreads();
        #pragma unroll
        for (int kk = 0; kk < 16; kk++) {
            float4 a4 = *(const float4*)&As[kk][4 * ty];
            float4 b4 = *(const float4*)&Bs[kk][4 * tx];
            float av[4] = {a4.x, a4.y, a4.z, a4.w};
            float bv[4] = {b4.x, b4.y, b4.z, b4.w};
            #pragma unroll
            for (int r = 0; r < 4; r++)
                #pragma unroll
                for (int c = 0; c < 4; c++)
                    acc[r][c] += av[r] * bv[c];
        }
        __syncthreads();
    }

    size_t mbase = (size_t)t * NBB;
    #pragma unroll
    for (int r = 0; r < 4; r++) {
        int b = 4 * ty + r;
        #pragma unroll
        for (int c = 0; c < 4; c++)
            C[(mbase + b) * NGG + n0 + 4 * tx + c] = acc[r][c];
    }
}

// ---------------- fused GRU layer step (split-K, 512 threads) -----------------
// Block: rows b0..b0+31, gate columns {i0..i0+15} x 3 gates (48 cols).
// 512 threads = two K-halves of 256 threads each; each half accumulates its
// partial SX/SH (layer1 fuses x@Wih^T and h@Whh^T in ONE k-loop), then halves
// are reduced in shared memory, followed by the GRU pointwise + masked update.
__global__ __launch_bounds__(512) void k_gru_layer(
    const float* __restrict__ gi,    // layer0: precomputed x-proj for this step; else null
    const float* __restrict__ xin,   // layer1: input rows [B,H]; else null
    const float* __restrict__ Wih,   // [3H,H] (used iff xin)
    const float* __restrict__ Whh,   // [3H,H]
    const float* __restrict__ bih,   // [3H]
    const float* __restrict__ bhh,   // [3H]
    const float* __restrict__ hin,   // [B,H] old hidden
    float* __restrict__ hout,        // [B,H] new hidden (other pingpong buf)
    float* __restrict__ xout,        // raw new hidden (layer input / top stash) or null
    const int* __restrict__ lens,    // encoder mask or null
    int t)
{
    __shared__ float SX[32][48];
    __shared__ float SH[32][48];
    __shared__ float Ah[2][16][33];
    __shared__ float Bh[2][16][49];
    __shared__ float Ax[2][16][33];
    __shared__ float Bx[2][16][49];

    int tid = threadIdx.x;
    int kz  = tid >> 8;              // K half: 0 -> [0,512), 1 -> [512,1024)
    int t2  = tid & 255;
    int ty  = t2 >> 4, tx = t2 & 15;
    int i0  = blockIdx.x * 16;
    int b0  = blockIdx.y * 32;
    int kbase = kz << 9;

    const bool fused = (gi == nullptr);   // layer1: compute SX too

    if (!fused) {
        // SX comes straight from precomputed gi
        for (int e = tid; e < 32 * 48; e += 512) {
            int rl = e / 48, c = e - rl * 48;
            int j = ((c >> 4) << 10) + i0 + (c & 15);
            SX[rl][c] = gi[(size_t)(b0 + rl) * NGG + j];
        }
    }

    float aH[2][3] = {};
    float aX[2][3] = {};

    for (int k0 = 0; k0 < 512; k0 += 16) {
        int kg = kbase + k0;
        #pragma unroll
        for (int e = t2; e < 512; e += 256) {
            int r = e >> 4, k = e & 15;
            Ah[kz][k][r] = hin[(size_t)(b0 + r) * NHH + kg + k];
        }
        #pragma unroll
        for (int e = t2; e < 768; e += 256) {
            int c = e >> 4, k = e & 15;
            int j = ((c >> 4) << 10) + i0 + (c & 15);
            Bh[kz][k][c] = Whh[(size_t)j * NHH + kg + k];
        }
        if (fused) {
            #pragma unroll
            for (int e = t2; e < 512; e += 256) {
                int r = e >> 4, k = e & 15;
                Ax[kz][k][r] = xin[(size_t)(b0 + r) * NHH + kg + k];
            }
            #pragma unroll
            for (int e = t2; e < 768; e += 256) {
                int c = e >> 4, k = e & 15;
                int j = ((c >> 4) << 10) + i0 + (c & 15);
                Bx[kz][k][c] = Wih[(size_t)j * NHH + kg + k];
            }
        }
        __syncthreads();
        if (fused) {
            #pragma unroll
            for (int kk = 0; kk < 16; kk++) {
                float h0 = Ah[kz][kk][2 * ty], h1 = Ah[kz][kk][2 * ty + 1];
                float x0 = Ax[kz][kk][2 * ty], x1 = Ax[kz][kk][2 * ty + 1];
                float wh0 = Bh[kz][kk][3 * tx], wh1 = Bh[kz][kk][3 * tx + 1], wh2 = Bh[kz][kk][3 * tx + 2];
                float wx0 = Bx[kz][kk][3 * tx], wx1 = Bx[kz][kk][3 * tx + 1], wx2 = Bx[kz][kk][3 * tx + 2];
                aH[0][0] += h0 * wh0; aH[0][1] += h0 * wh1; aH[0][2] += h0 * wh2;
                aH[1][0] += h1 * wh0; aH[1][1] += h1 * wh1; aH[1][2] += h1 * wh2;
                aX[0][0] += x0 * wx0; aX[0][1] += x0 * wx1; aX[0][2] += x0 * wx2;
                aX[1][0] += x1 * wx0; aX[1][1] += x1 * wx1; aX[1][2] += x1 * wx2;
            }
        } else {
            #pragma unroll
            for (int kk = 0; kk < 16; kk++) {
                float h0 = Ah[kz][kk][2 * ty], h1 = Ah[kz][kk][2 * ty + 1];
                float wh0 = Bh[kz][kk][3 * tx], wh1 = Bh[kz][kk][3 * tx + 1], wh2 = Bh[kz][kk][3 * tx + 2];
                aH[0][0] += h0 * wh0; aH[0][1] += h0 * wh1; aH[0][2] += h0 * wh2;
                aH[1][0] += h1 * wh0; aH[1][1] += h1 * wh1; aH[1][2] += h1 * wh2;
            }
        }
        __syncthreads();
    }

    // ---- cross-half reduction into SX/SH ----
    if (kz == 0) {
        #pragma unroll
        for (int r = 0; r < 2; r++)
            #pragma unroll
            for (int c = 0; c < 3; c++) {
                SH[2 * ty + r][3 * tx + c] = aH[r][c];
                if (fused) SX[2 * ty + r][3 * tx + c] = aX[r][c];
            }
    }
    __syncthreads();
    if (kz == 1) {
        #pragma unroll
        for (int r = 0; r < 2; r++)
            #pragma unroll
            for (int c = 0; c < 3; c++) {
                SH[2 * ty + r][3 * tx + c] += aH[r][c];
                if (fused) SX[2 * ty + r][3 * tx + c] += aX[r][c];
            }
    }
    __syncthreads();

    // ---- GRU pointwise + masked state update (512 threads, 1 output each) ----
    {
        int rl = tid >> 4, il = tid & 15;
        int b = b0 + rl, i = i0 + il;
        float xr = SX[rl][il]      + bih[i];
        float xz = SX[rl][16 + il] + bih[NHH + i];
        float xn = SX[rl][32 + il] + bih[2 * NHH + i];
        float hr = SH[rl][il]      + bhh[i];
        float hz = SH[rl][16 + il] + bhh[NHH + i];
        float hn = SH[rl][32 + il] + bhh[2 * NHH + i];
        float r = 1.0f / (1.0f + expf(-(xr + hr)));
        float z = 1.0f / (1.0f + expf(-(xz + hz)));
        float n = tanhf(xn + r * hn);
        float hold = hin[(size_t)b * NHH + i];
        float hnew = (1.0f - z) * n + z * hold;
        float hw = hnew;
        if (lens && !(t < lens[b])) hw = hold;   // freeze past sequence end
        hout[(size_t)b * NHH + i] = hw;
        if (xout) xout[(size_t)b * NHH + i] = hnew;  // raw output feeds next layer
    }
}

// ---------------- output projection GEMM --------------------------------------
// logits[m, n] = dot(top[m,:], Wout[n,:]) + bout[n], m = t*64 + b (t in 0..62)
// scattered to out[b, t+1, n].
__global__ __launch_bounds__(256) void k_out_gemm(
    const float* __restrict__ A,     // g_top [4032, 1024]
    const float* __restrict__ W,     // Wout  [32000, 1024]
    const float* __restrict__ bo,    // [32000]
    float* __restrict__ out)         // [B, T, V]
{
    __shared__ __align__(16) float As[16][68];
    __shared__ __align__(16) float Bs[16][68];

    int m0 = blockIdx.x * 64;
    int n0 = blockIdx.y * 64;
    int tid = threadIdx.x;
    int ty = tid >> 4, tx = tid & 15;

    float acc[4][4] = {};
    for (int k0 = 0; k0 < NHH; k0 += 16) {
        #pragma unroll
        for (int e = tid; e < 1024; e += 256) {
            int r = e >> 4, k = e & 15;
            As[k][r] = A[(size_t)(m0 + r) * NHH + k0 + k];
            Bs[k][r] = W[(size_t)(n0 + r) * NHH + k0 + k];
        }
        __syncthreads();
        #pragma unroll
        for (int kk = 0; kk < 16; kk++) {
            float4 a4 = *(const float4*)&As[kk][4 * ty];
            float4 b4 = *(const float4*)&Bs[kk][4 * tx];
            float av[4] = {a4.x, a4.y, a4.z, a4.w};
            float bv[4] = {b4.x, b4.y, b4.z, b4.w};
            #pragma unroll
            for (int r = 0; r < 4; r++)
                #pragma unroll
                for (int c = 0; c < 4; c++)
                    acc[r][c] += av[r] * bv[c];
        }
        __syncthreads();
    }

    #pragma unroll
    for (int r = 0; r < 4; r++) {
        int m = m0 + 4 * ty + r;
        int b = m & 63;
        int t = m >> 6;                  // 0..62
        size_t obase = (size_t)b * NTT * NVV + (size_t)(t + 1) * NVV;
        #pragma unroll
        for (int c = 0; c < 4; c++) {
            int n = n0 + 4 * tx + c;
            out[obase + n] = acc[r][c] + bo[n];
        }
    }
}

// ---------------- launch ------------------------------------------------------
extern "C" void kernel_launch(void* const* d_in, const int* in_sizes, int n_in,
                              void* d_out, int out_size)
{
    const int*   src_tokens  = (const int*)d_in[0];
    const int*   src_lengths = (const int*)d_in[1];
    const int*   trg         = (const int*)d_in[2];
    const float* emb_enc     = (const float*)d_in[3];
    const float* Wih_enc     = (const float*)d_in[4];
    const float* Whh_enc     = (const float*)d_in[5];
    const float* bih_enc     = (const float*)d_in[6];
    const float* bhh_enc     = (const float*)d_in[7];
    const float* emb_dec     = (const float*)d_in[8];
    const float* Wih_dec     = (const float*)d_in[9];
    const float* Whh_dec     = (const float*)d_in[10];
    const float* bih_dec     = (const float*)d_in[11];
    const float* bhh_dec     = (const float*)d_in[12];
    const float* Wout        = (const float*)d_in[13];
    const float* bout        = (const float*)d_in[14];
    float* out = (float*)d_out;

    float *gi_enc, *gi_dec, *hbuf, *x1, *top;
    cudaGetSymbolAddress((void**)&gi_enc, g_gi_enc);
    cudaGetSymbolAddress((void**)&gi_dec, g_gi_dec);
    cudaGetSymbolAddress((void**)&hbuf,  g_hbuf);
    cudaGetSymbolAddress((void**)&x1,    g_x1);
    cudaGetSymbolAddress((void**)&top,   g_top);

    const int HB = NBB * NHH;   // 65536 floats per (layer) hidden

    // initial hidden (pingpong buf 0, both layers) and out[:,0,:]
    k_zero<<<(2 * HB + 255) / 256, 256>>>(hbuf, 2 * HB);
    k_zero_out_t0<<<(NBB * NVV + 255) / 256, 256>>>(out);

    // encoder layer-0 input projections for all timesteps (one big GEMM)
    dim3 eg(NSS, NGG / 64);
    k_embed_gemm<<<eg, 256>>>(src_tokens, NSS, emb_enc, Wih_enc, gi_enc);

    dim3 gg(NHH / 16, 2);
    for (int t = 0; t < NSS; t++) {
        float* hr = hbuf + (size_t)(t & 1) * 2 * HB;
        float* hw = hbuf + (size_t)((t + 1) & 1) * 2 * HB;
        // layer 0
        k_gru_layer<<<gg, 512>>>(gi_enc + (size_t)t * NBB * NGG, nullptr,
                                 nullptr, Whh_enc, bih_enc, bhh_enc,
                                 hr, hw, x1, src_lengths, t);
        // layer 1 (fused x/h GEMMs)
        k_gru_layer<<<gg, 512>>>(nullptr, x1,
                                 Wih_enc + (size_t)NGG * NEE, Whh_enc + (size_t)NGG * NHH,
                                 bih_enc + NGG, bhh_enc + NGG,
                                 hr + HB, hw + HB, nullptr, src_lengths, t);
    }

    // decoder layer-0 input projections (teacher forcing: tokens known upfront)
    dim3 dg(NTT - 1, NGG / 64);
    k_embed_gemm<<<dg, 256>>>(trg, NTT, emb_dec, Wih_dec, gi_dec);

    for (int k = 0; k < NTT - 1; k++) {
        float* hr = hbuf + (size_t)(k & 1) * 2 * HB;
        float* hw = hbuf + (size_t)((k + 1) & 1) * 2 * HB;
        k_gru_layer<<<gg, 512>>>(gi_dec + (size_t)k * NBB * NGG, nullptr,
                                 nullptr, Whh_dec, bih_dec, bhh_dec,
                                 hr, hw, x1, nullptr, k);
        k_gru_layer<<<gg, 512>>>(nullptr, x1,
                                 Wih_dec + (size_t)NGG * NEE, Whh_dec + (size_t)NGG * NHH,
                                 bih_dec + NGG, bhh_dec + NGG,
                                 hr + HB, hw + HB, top + (size_t)k * HB, nullptr, k);
    }

    // one deferred output projection over all decoder steps
    dim3 og((NTT - 1) * NBB / 64, NVV / 64);   // (63, 500)
    k_out_gemm<<<og, 256>>>(top, Wout, bout, out);
}

// round 17
// speedup vs baseline: 1.2206x; 1.0009x over previous
#include <cuda_runtime.h>
#include <math.h>
#include <stdint.h>

#define NBB 64      // batch
#define NSS 64      // src len
#define NTT 64      // trg len
#define NEE 1024    // embed dim
#define NHH 1024    // hidden
#define NGG 3072    // 3*H
#define NVV 32000   // vocab

// ---------------- scratch (device globals; no cudaMalloc allowed) ------------
__device__ float g_gi_enc[NSS * NBB * NGG];          // enc layer0 x-projection, all t
__device__ float g_gi_dec[(NTT - 1) * NBB * NGG];    // dec layer0 x-projection, all t
__device__ float g_hbuf[2 * 2 * NBB * NHH];          // [pingpong][layer][B*H]
__device__ float g_x1[NBB * NHH];                    // layer0 -> layer1 input
__device__ float g_top[(NTT - 1) * NBB * NHH];       // decoder top hidden states

// ---------------- small utility kernels --------------------------------------
__global__ void k_zero(float* p, int n) {
    int i = blockIdx.x * blockDim.x + threadIdx.x;
    if (i < n) p[i] = 0.0f;
}

__global__ void k_zero_out_t0(float* out) {
    int i = blockIdx.x * blockDim.x + threadIdx.x;
    if (i < NBB * NVV) {
        int b = i / NVV, v = i - b * NVV;
        out[(size_t)b * NTT * NVV + v] = 0.0f;
    }
}

// ---------------- embedding-gather GEMM ---------------------------------------
// C[(t*64 + b)*NG + j] = dot(emb[tokens[b*tokStride + t]], W[j, :])
__global__ __launch_bounds__(256) void k_embed_gemm(
    const int* __restrict__ tokens, int tokStride,
    const float* __restrict__ emb,      // [V, E]
    const float* __restrict__ W,        // [3H, E]
    float* __restrict__ C)              // [steps*64, 3H]
{
    __shared__ __align__(16) float As[16][68];
    __shared__ __align__(16) float Bs[16][68];
    __shared__ int tok_s[64];

    int t  = blockIdx.x;
    int n0 = blockIdx.y * 64;
    int tid = threadIdx.x;
    int ty = tid >> 4, tx = tid & 15;

    if (tid < 64) tok_s[tid] = tokens[tid * tokStride + t];
    __syncthreads();

    float acc[4][4] = {};
    for (int k0 = 0; k0 < NEE; k0 += 16) {
        #pragma unroll
        for (int e = tid; e < 1024; e += 256) {
            int r = e >> 4, k = e & 15;
            As[k][r] = emb[(size_t)tok_s[r] * NEE + k0 + k];
            Bs[k][r] = W[(size_t)(n0 + r) * NEE + k0 + k];
        }
        __syncthreads();
        #pragma unroll
        for (int kk = 0; kk < 16; kk++) {
            float4 a4 = *(const float4*)&As[kk][4 * ty];
            float4 b4 = *(const float4*)&Bs[kk][4 * tx];
            float av[4] = {a4.x, a4.y, a4.z, a4.w};
            float bv[4] = {b4.x, b4.y, b4.z, b4.w};
            #pragma unroll
            for (int r = 0; r < 4; r++)
                #pragma unroll
                for (int c = 0; c < 4; c++)
                    acc[r][c] += av[r] * bv[c];
        }
        __syncthreads();
    }

    size_t mbase = (size_t)t * NBB;
    #pragma unroll
    for (int r = 0; r < 4; r++) {
        int b = 4 * ty + r;
        #pragma unroll
        for (int c = 0; c < 4; c++)
            C[(mbase + b) * NGG + n0 + 4 * tx + c] = acc[r][c];
    }
}

// ---------------- fused GRU layer step (split-K, 512 threads) -----------------
// Block: rows b0..b0+31, gate columns {i0..i0+15} x 3 gates (48 cols).
// 512 threads = two K-halves of 256 threads each; each half accumulates its
// partial SX/SH (layer1 fuses x@Wih^T and h@Whh^T in ONE k-loop), then halves
// are reduced in shared memory, followed by the GRU pointwise + masked update.
__global__ __launch_bounds__(512) void k_gru_layer(
    const float* __restrict__ gi,    // layer0: precomputed x-proj for this step; else null
    const float* __restrict__ xin,   // layer1: input rows [B,H]; else null
    const float* __restrict__ Wih,   // [3H,H] (used iff xin)
    const float* __restrict__ Whh,   // [3H,H]
    const float* __restrict__ bih,   // [3H]
    const float* __restrict__ bhh,   // [3H]
    const float* __restrict__ hin,   // [B,H] old hidden
    float* __restrict__ hout,        // [B,H] new hidden (other pingpong buf)
    float* __restrict__ xout,        // raw new hidden (layer input / top stash) or null
    const int* __restrict__ lens,    // encoder mask or null
    int t)
{
    __shared__ float SX[32][48];
    __shared__ float SH[32][48];
    __shared__ float Ah[2][16][33];
    __shared__ float Bh[2][16][49];
    __shared__ float Ax[2][16][33];
    __shared__ float Bx[2][16][49];

    int tid = threadIdx.x;
    int kz  = tid >> 8;              // K half: 0 -> [0,512), 1 -> [512,1024)
    int t2  = tid & 255;
    int ty  = t2 >> 4, tx = t2 & 15;
    int i0  = blockIdx.x * 16;
    int b0  = blockIdx.y * 32;
    int kbase = kz << 9;

    const bool fused = (gi == nullptr);   // layer1: compute SX too

    if (!fused) {
        // SX comes straight from precomputed gi
        for (int e = tid; e < 32 * 48; e += 512) {
            int rl = e / 48, c = e - rl * 48;
            int j = ((c >> 4) << 10) + i0 + (c & 15);
            SX[rl][c] = gi[(size_t)(b0 + rl) * NGG + j];
        }
    }

    float aH[2][3] = {};
    float aX[2][3] = {};

    for (int k0 = 0; k0 < 512; k0 += 16) {
        int kg = kbase + k0;
        #pragma unroll
        for (int e = t2; e < 512; e += 256) {
            int r = e >> 4, k = e & 15;
            Ah[kz][k][r] = hin[(size_t)(b0 + r) * NHH + kg + k];
        }
        #pragma unroll
        for (int e = t2; e < 768; e += 256) {
            int c = e >> 4, k = e & 15;
            int j = ((c >> 4) << 10) + i0 + (c & 15);
            Bh[kz][k][c] = Whh[(size_t)j * NHH + kg + k];
        }
        if (fused) {
            #pragma unroll
            for (int e = t2; e < 512; e += 256) {
                int r = e >> 4, k = e & 15;
                Ax[kz][k][r] = xin[(size_t)(b0 + r) * NHH + kg + k];
            }
            #pragma unroll
            for (int e = t2; e < 768; e += 256) {
                int c = e >> 4, k = e & 15;
                int j = ((c >> 4) << 10) + i0 + (c & 15);
                Bx[kz][k][c] = Wih[(size_t)j * NHH + kg + k];
            }
        }
        __syncthreads();
        if (fused) {
            #pragma unroll
            for (int kk = 0; kk < 16; kk++) {
                float h0 = Ah[kz][kk][2 * ty], h1 = Ah[kz][kk][2 * ty + 1];
                float x0 = Ax[kz][kk][2 * ty], x1 = Ax[kz][kk][2 * ty + 1];
                float wh0 = Bh[kz][kk][3 * tx], wh1 = Bh[kz][kk][3 * tx + 1], wh2 = Bh[kz][kk][3 * tx + 2];
                float wx0 = Bx[kz][kk][3 * tx], wx1 = Bx[kz][kk][3 * tx + 1], wx2 = Bx[kz][kk][3 * tx + 2];
                aH[0][0] += h0 * wh0; aH[0][1] += h0 * wh1; aH[0][2] += h0 * wh2;
                aH[1][0] += h1 * wh0; aH[1][1] += h1 * wh1; aH[1][2] += h1 * wh2;
                aX[0][0] += x0 * wx0; aX[0][1] += x0 * wx1; aX[0][2] += x0 * wx2;
                aX[1][0] += x1 * wx0; aX[1][1] += x1 * wx1; aX[1][2] += x1 * wx2;
            }
        } else {
            #pragma unroll
            for (int kk = 0; kk < 16; kk++) {
                float h0 = Ah[kz][kk][2 * ty], h1 = Ah[kz][kk][2 * ty + 1];
                float wh0 = Bh[kz][kk][3 * tx], wh1 = Bh[kz][kk][3 * tx + 1], wh2 = Bh[kz][kk][3 * tx + 2];
                aH[0][0] += h0 * wh0; aH[0][1] += h0 * wh1; aH[0][2] += h0 * wh2;
                aH[1][0] += h1 * wh0; aH[1][1] += h1 * wh1; aH[1][2] += h1 * wh2;
            }
        }
        __syncthreads();
    }

    // ---- cross-half reduction into SX/SH ----
    if (kz == 0) {
        #pragma unroll
        for (int r = 0; r < 2; r++)
            #pragma unroll
            for (int c = 0; c < 3; c++) {
                SH[2 * ty + r][3 * tx + c] = aH[r][c];
                if (fused) SX[2 * ty + r][3 * tx + c] = aX[r][c];
            }
    }
    __syncthreads();
    if (kz == 1) {
        #pragma unroll
        for (int r = 0; r < 2; r++)
            #pragma unroll
            for (int c = 0; c < 3; c++) {
                SH[2 * ty + r][3 * tx + c] += aH[r][c];
                if (fused) SX[2 * ty + r][3 * tx + c] += aX[r][c];
            }
    }
    __syncthreads();

    // ---- GRU pointwise + masked state update (512 threads, 1 output each) ----
    {
        int rl = tid >> 4, il = tid & 15;
        int b = b0 + rl, i = i0 + il;
        float xr = SX[rl][il]      + bih[i];
        float xz = SX[rl][16 + il] + bih[NHH + i];
        float xn = SX[rl][32 + il] + bih[2 * NHH + i];
        float hr = SH[rl][il]      + bhh[i];
        float hz = SH[rl][16 + il] + bhh[NHH + i];
        float hn = SH[rl][32 + il] + bhh[2 * NHH + i];
        float r = 1.0f / (1.0f + expf(-(xr + hr)));
        float z = 1.0f / (1.0f + expf(-(xz + hz)));
        float n = tanhf(xn + r * hn);
        float hold = hin[(size_t)b * NHH + i];
        float hnew = (1.0f - z) * n + z * hold;
        float hw = hnew;
        if (lens && !(t < lens[b])) hw = hold;   // freeze past sequence end
        hout[(size_t)b * NHH + i] = hw;
        if (xout) xout[(size_t)b * NHH + i] = hnew;  // raw output feeds next layer
    }
}

// ---------------- output projection GEMM --------------------------------------
// logits[m, n] = dot(top[m,:], Wout[n,:]) + bout[n], m = t*64 + b (t in 0..62)
// scattered to out[b, t+1, n].
__global__ __launch_bounds__(256) void k_out_gemm(
    const float* __restrict__ A,     // g_top [4032, 1024]
    const float* __restrict__ W,     // Wout  [32000, 1024]
    const float* __restrict__ bo,    // [32000]
    float* __restrict__ out)         // [B, T, V]
{
    __shared__ __align__(16) float As[16][68];
    __shared__ __align__(16) float Bs[16][68];

    int m0 = blockIdx.x * 64;
    int n0 = blockIdx.y * 64;
    int tid = threadIdx.x;
    int ty = tid >> 4, tx = tid & 15;

    float acc[4][4] = {};
    for (int k0 = 0; k0 < NHH; k0 += 16) {
        #pragma unroll
        for (int e = tid; e < 1024; e += 256) {
            int r = e >> 4, k = e & 15;
            As[k][r] = A[(size_t)(m0 + r) * NHH + k0 + k];
            Bs[k][r] = W[(size_t)(n0 + r) * NHH + k0 + k];
        }
        __syncthreads();
        #pragma unroll
        for (int kk = 0; kk < 16; kk++) {
            float4 a4 = *(const float4*)&As[kk][4 * ty];
            float4 b4 = *(const float4*)&Bs[kk][4 * tx];
            float av[4] = {a4.x, a4.y, a4.z, a4.w};
            float bv[4] = {b4.x, b4.y, b4.z, b4.w};
            #pragma unroll
            for (int r = 0; r < 4; r++)
                #pragma unroll
                for (int c = 0; c < 4; c++)
                    acc[r][c] += av[r] * bv[c];
        }
        __syncthreads();
    }

    #pragma unroll
    for (int r = 0; r < 4; r++) {
        int m = m0 + 4 * ty + r;
        int b = m & 63;
        int t = m >> 6;                  // 0..62
        size_t obase = (size_t)b * NTT * NVV + (size_t)(t + 1) * NVV;
        #pragma unroll
        for (int c = 0; c < 4; c++) {
            int n = n0 + 4 * tx + c;
            out[obase + n] = acc[r][c] + bo[n];
        }
    }
}

// ---------------- launch ------------------------------------------------------
extern "C" void kernel_launch(void* const* d_in, const int* in_sizes, int n_in,
                              void* d_out, int out_size)
{
    const int*   src_tokens  = (const int*)d_in[0];
    const int*   src_lengths = (const int*)d_in[1];
    const int*   trg         = (const int*)d_in[2];
    const float* emb_enc     = (const float*)d_in[3];
    const float* Wih_enc     = (const float*)d_in[4];
    const float* Whh_enc     = (const float*)d_in[5];
    const float* bih_enc     = (const float*)d_in[6];
    const float* bhh_enc     = (const float*)d_in[7];
    const float* emb_dec     = (const float*)d_in[8];
    const float* Wih_dec     = (const float*)d_in[9];
    const float* Whh_dec     = (const float*)d_in[10];
    const float* bih_dec     = (const float*)d_in[11];
    const float* bhh_dec     = (const float*)d_in[12];
    const float* Wout        = (const float*)d_in[13];
    const float* bout        = (const float*)d_in[14];
    float* out = (float*)d_out;

    float *gi_enc, *gi_dec, *hbuf, *x1, *top;
    cudaGetSymbolAddress((void**)&gi_enc, g_gi_enc);
    cudaGetSymbolAddress((void**)&gi_dec, g_gi_dec);
    cudaGetSymbolAddress((void**)&hbuf,  g_hbuf);
    cudaGetSymbolAddress((void**)&x1,    g_x1);
    cudaGetSymbolAddress((void**)&top,   g_top);

    const int HB = NBB * NHH;   // 65536 floats per (layer) hidden

    // initial hidden (pingpong buf 0, both layers) and out[:,0,:]
    k_zero<<<(2 * HB + 255) / 256, 256>>>(hbuf, 2 * HB);
    k_zero_out_t0<<<(NBB * NVV + 255) / 256, 256>>>(out);

    // encoder layer-0 input projections for all timesteps (one big GEMM)
    dim3 eg(NSS, NGG / 64);
    k_embed_gemm<<<eg, 256>>>(src_tokens, NSS, emb_enc, Wih_enc, gi_enc);

    dim3 gg(NHH / 16, 2);
    for (int t = 0; t < NSS; t++) {
        float* hr = hbuf + (size_t)(t & 1) * 2 * HB;
        float* hw = hbuf + (size_t)((t + 1) & 1) * 2 * HB;
        // layer 0
        k_gru_layer<<<gg, 512>>>(gi_enc + (size_t)t * NBB * NGG, nullptr,
                                 nullptr, Whh_enc, bih_enc, bhh_enc,
                                 hr, hw, x1, src_lengths, t);
        // layer 1 (fused x/h GEMMs)
        k_gru_layer<<<gg, 512>>>(nullptr, x1,
                                 Wih_enc + (size_t)NGG * NEE, Whh_enc + (size_t)NGG * NHH,
                                 bih_enc + NGG, bhh_enc + NGG,
                                 hr + HB, hw + HB, nullptr, src_lengths, t);
    }

    // decoder layer-0 input projections (teacher forcing: tokens known upfront)
    dim3 dg(NTT - 1, NGG / 64);
    k_embed_gemm<<<dg, 256>>>(trg, NTT, emb_dec, Wih_dec, gi_dec);

    for (int k = 0; k < NTT - 1; k++) {
        float* hr = hbuf + (size_t)(k & 1) * 2 * HB;
        float* hw = hbuf + (size_t)((k + 1) & 1) * 2 * HB;
        k_gru_layer<<<gg, 512>>>(gi_dec + (size_t)k * NBB * NGG, nullptr,
                                 nullptr, Whh_dec, bih_dec, bhh_dec,
                                 hr, hw, x1, nullptr, k);
        k_gru_layer<<<gg, 512>>>(nullptr, x1,
                                 Wih_dec + (size_t)NGG * NEE, Whh_dec + (size_t)NGG * NHH,
                                 bih_dec + NGG, bhh_dec + NGG,
                                 hr + HB, hw + HB, top + (size_t)k * HB, nullptr, k);
    }

    // one deferred output projection over all decoder steps
    dim3 og((NTT - 1) * NBB / 64, NVV / 64);   // (63, 500)
    k_out_gemm<<<og, 256>>>(top, Wout, bout, out);
}